// round 12
// baseline (speedup 1.0000x reference)
#include <cuda_runtime.h>
#include <cuda_fp16.h>
#include <cstdint>

#define B_DIM 4096
#define T_DIM 200
#define NEG_INF (-4294967295.0f)
#define KROW 144          // f16 key row stride bytes (36 words; 36 mod 32 = 4)

// smem byte offsets
#define OFF_K    0        // f16 keys: 416 rows x KROW (row1 block starts at row 208)
#define OFF_WT   59904    // weight tables hi|lo, 9216 B
#define OFF_QH   69120    // f32 qh[2][32]
#define OFF_W2   69376    // f32 w2[32]
#define OFF_SC   69504    // f32 scores[2][208]
#define OFF_RED  71168    // f32 red[16]: [row*4+w4] max, [8+row*4+w4] sum
#define OFF_OP   71232    // float2 opart[2][4][32]
#define SMEM_BYTES 73280

__device__ float    g_wq[2048];    // W1a + W1c
__device__ uint32_t g_wtab[2304];  // [0,1152): f16x2 hi fragments; [1152,2304): lo

__global__ __launch_bounds__(256)
void setup_kernel(const float* __restrict__ W1)
{
    const int tid = threadIdx.x, blk = blockIdx.x;
    if (blk < 8) {
        const int i = blk * 256 + tid;
        g_wq[i] = W1[i] + W1[4096 + i];
        return;
    }
    const int idx = (blk - 8) * 256 + tid;
    int d2 = idx >> 5, j = idx & 31, k = 2 * d2;
    float w0 = W1[2048 + k * 32 + j] - W1[4096 + k * 32 + j];
    float w1 = W1[2048 + (k + 1) * 32 + j] - W1[4096 + (k + 1) * 32 + j];
    uint32_t hi, lo;
    asm("cvt.rn.f16x2.f32 %0, %1, %2;" : "=r"(hi) : "f"(w1), "f"(w0));
    float h0f = __half2float(__ushort_as_half((unsigned short)(hi & 0xFFFFu)));
    float h1f = __half2float(__ushort_as_half((unsigned short)(hi >> 16)));
    asm("cvt.rn.f16x2.f32 %0, %1, %2;" : "=r"(lo) : "f"(w1 - h1f), "f"(w0 - h0f));
    int ks = d2 >> 3, k2 = d2 & 7, t4 = k2 & 3, sel = k2 >> 2;
    int word = ks * 288 + t4 * 72 + j * 2 + sel;
    g_wtab[word]        = hi;
    g_wtab[1152 + word] = lo;
}

static __device__ __forceinline__ float sigmoidf_fast(float h) {
    return __fdividef(1.0f, 1.0f + __expf(-h));
}

__global__ __launch_bounds__(256, 3)
void attn_pool_kernel(const float* __restrict__ query,
                      const float* __restrict__ keys,
                      const unsigned char* __restrict__ mask_raw,
                      const float* __restrict__ b1,
                      const float* __restrict__ W2,
                      const float* __restrict__ b2,
                      float* __restrict__ out)
{
    extern __shared__ char sm[];
    float* smf = (float*)sm;
    const int b    = blockIdx.x;           // batch rows 2b, 2b+1
    const int tid  = threadIdx.x;
    const int lane = tid & 31;
    const int wid  = tid >> 5;
    const int g    = lane >> 2;
    const int t4   = lane & 3;
    uint32_t sbase;
    asm("{ .reg .u64 t; cvta.to.shared.u64 t, %1; cvt.u32.u64 %0, t; }"
        : "=r"(sbase) : "l"(sm));
    const float4* kb = (const float4*)(keys + (size_t)b * 25600);

    // ---- stage weight tables via cp.async ----
    for (int i = tid; i < 576; i += 256)
        asm volatile("cp.async.cg.shared.global [%0], [%1], 16;"
                     :: "r"(sbase + OFF_WT + i * 16), "l"((const char*)g_wtab + i * 16));
    asm volatile("cp.async.commit_group;" ::: "memory");

    // ---- stage both rows' keys: fp32 LDG.128 -> f16x2 -> STS.64 ----
    #pragma unroll 5
    for (int i = tid; i < 6400; i += 256) {
        float4 v = __ldg(kb + i);
        int r = i >> 4, c = i & 15;
        int rr = r + ((r >= 200) ? 8 : 0);
        uint32_t p0, p1;
        asm("cvt.rn.f16x2.f32 %0,%1,%2;" : "=r"(p0) : "f"(v.y), "f"(v.x));
        asm("cvt.rn.f16x2.f32 %0,%1,%2;" : "=r"(p1) : "f"(v.w), "f"(v.z));
        asm volatile("st.shared.v2.b32 [%0],{%1,%2};"
                     :: "r"(sbase + OFF_K + rr * KROW + c * 8), "r"(p0), "r"(p1));
    }
    // zero pad rows 200..207 and 408..415
    for (int i = tid; i < 576; i += 256) {
        int rblk = i / 36, w = i - rblk * 36;
        int rr = (rblk < 8) ? (200 + rblk) : (400 + rblk);
        smf[(OFF_K + rr * KROW) / 4 + w] = 0.0f;
    }

    // ---- warps 0,1: qh per row ; warp 2: w2 ----
    if (wid < 2) {
        const float* qrow = query + (size_t)(2 * b + wid) * 64;
        float q0 = qrow[lane], q1 = qrow[32 + lane];
        float s = b1[lane];
        #pragma unroll
        for (int d = 0; d < 32; d++)
            s = fmaf(__shfl_sync(0xffffffffu, q0, d), g_wq[d * 32 + lane], s);
        #pragma unroll
        for (int d = 0; d < 32; d++)
            s = fmaf(__shfl_sync(0xffffffffu, q1, d), g_wq[(32 + d) * 32 + lane], s);
        smf[OFF_QH / 4 + wid * 32 + lane] = s;
    }
    if (wid == 2) smf[OFF_W2 / 4 + lane] = __ldg(W2 + lane);

    // ---- mask dtype detect + per-tile mask bits + b2 ----
    int my_nz = 0;
    #pragma unroll
    for (int w = lane; w < 256; w += 32)
        my_nz |= mask_raw[4 * w + 1] | mask_raw[4 * w + 2] | mask_raw[4 * w + 3];
    const bool mode_u8 = __any_sync(0xffffffffu, my_nz != 0);
    const int* mask_i32 = (const int*)mask_raw;
    const float b2v = __ldg(b2);

    int mval = 0;
    if (t4 == 0) {
        #pragma unroll
        for (int slot = 0; slot < 4; slot++) {
            int tt = wid + 8 * (slot & 1) + 16 * (slot >> 1);
            if (tt >= 26) continue;
            int row = (tt >= 13) ? 1 : 0;
            int m0 = (tt - row * 13) * 16;
            long gb = (long)(2 * b + row) * T_DIM;
            int r0 = m0 + g;
            bool v0 = mode_u8 ? (mask_raw[gb + r0] != 0) : (mask_i32[gb + r0] != 0);
            mval |= (int)v0 << (2 * slot);
            int r1 = r0 + 8;
            if (r1 < T_DIM) {
                bool v1 = mode_u8 ? (mask_raw[gb + r1] != 0) : (mask_i32[gb + r1] != 0);
                mval |= (int)v1 << (2 * slot + 1);
            }
        }
    }

    asm volatile("cp.async.wait_group 0;" ::: "memory");
    __syncthreads();

    // ====== score GEMM: 26 m-tiles over both rows, two passes ======
    #pragma unroll
    for (int pass = 0; pass < 2; pass++) {
        float acc[2][4][4];
        #pragma unroll
        for (int mi = 0; mi < 2; mi++)
            #pragma unroll
            for (int nt = 0; nt < 4; nt++)
                #pragma unroll
                for (int e = 0; e < 4; e++) acc[mi][nt][e] = 0.0f;

        #pragma unroll
        for (int ks = 0; ks < 4; ks++) {
            const uint32_t wrow = sbase + OFF_WT + (uint32_t)(ks * 1152 + t4 * 288 + g * 8);
            uint2 bh[4], bl[4];
            #pragma unroll
            for (int nt = 0; nt < 4; nt++) {
                asm("ld.shared.v2.u32 {%0,%1},[%2];"
                    : "=r"(bh[nt].x), "=r"(bh[nt].y) : "r"(wrow + nt * 64));
                asm("ld.shared.v2.u32 {%0,%1},[%2];"
                    : "=r"(bl[nt].x), "=r"(bl[nt].y) : "r"(wrow + nt * 64 + 4608));
            }
            #pragma unroll
            for (int mi = 0; mi < 2; mi++) {
                int tt = wid + 8 * mi + 16 * pass;
                if (tt >= 26) continue;
                int row = (tt >= 13) ? 1 : 0;
                int m0 = (tt - row * 13) * 16;
                const uint32_t abase = sbase + OFF_K +
                    (uint32_t)((row * 208 + m0 + g) * KROW + ks * 32 + t4 * 4);
                uint32_t a0, a1, a2, a3;
                asm("ld.shared.b32 %0,[%1];" : "=r"(a0) : "r"(abase));
                asm("ld.shared.b32 %0,[%1];" : "=r"(a2) : "r"(abase + 16));
                asm("ld.shared.b32 %0,[%1];" : "=r"(a1) : "r"(abase + 8 * KROW));
                asm("ld.shared.b32 %0,[%1];" : "=r"(a3) : "r"(abase + 8 * KROW + 16));
                #pragma unroll
                for (int nt = 0; nt < 4; nt++) {
                    asm volatile(
                        "mma.sync.aligned.m16n8k16.row.col.f32.f16.f16.f32 "
                        "{%0,%1,%2,%3}, {%4,%5,%6,%7}, {%8,%9}, {%0,%1,%2,%3};"
                        : "+f"(acc[mi][nt][0]), "+f"(acc[mi][nt][1]),
                          "+f"(acc[mi][nt][2]), "+f"(acc[mi][nt][3])
                        : "r"(a0), "r"(a1), "r"(a2), "r"(a3),
                          "r"(bh[nt].x), "r"(bh[nt].y));
                    asm volatile(
                        "mma.sync.aligned.m16n8k16.row.col.f32.f16.f16.f32 "
                        "{%0,%1,%2,%3}, {%4,%5,%6,%7}, {%8,%9}, {%0,%1,%2,%3};"
                        : "+f"(acc[mi][nt][0]), "+f"(acc[mi][nt][1]),
                          "+f"(acc[mi][nt][2]), "+f"(acc[mi][nt][3])
                        : "r"(a0), "r"(a1), "r"(a2), "r"(a3),
                          "r"(bl[nt].x), "r"(bl[nt].y));
                }
            }
        }

        // epilogue for this pass's tiles
        #pragma unroll
        for (int mi = 0; mi < 2; mi++) {
            int tt = wid + 8 * mi + 16 * pass;
            if (tt >= 26) continue;
            int row = (tt >= 13) ? 1 : 0;
            int m0 = (tt - row * 13) * 16;
            int slot = 2 * pass + mi;
            float s_lo = 0.0f, s_hi = 0.0f;
            #pragma unroll
            for (int nt = 0; nt < 4; nt++) {
                const int j0 = 8 * nt + 2 * t4;
                float2 qh2 = *(float2*)(sm + OFF_QH + row * 128 + j0 * 4);
                float2 w22 = *(float2*)(sm + OFF_W2 + j0 * 4);
                s_lo = fmaf(sigmoidf_fast(acc[mi][nt][0] + qh2.x), w22.x, s_lo);
                s_lo = fmaf(sigmoidf_fast(acc[mi][nt][1] + qh2.y), w22.y, s_lo);
                s_hi = fmaf(sigmoidf_fast(acc[mi][nt][2] + qh2.x), w22.x, s_hi);
                s_hi = fmaf(sigmoidf_fast(acc[mi][nt][3] + qh2.y), w22.y, s_hi);
            }
            s_lo += __shfl_xor_sync(0xffffffffu, s_lo, 1);
            s_lo += __shfl_xor_sync(0xffffffffu, s_lo, 2);
            s_hi += __shfl_xor_sync(0xffffffffu, s_hi, 1);
            s_hi += __shfl_xor_sync(0xffffffffu, s_hi, 2);
            if (t4 == 0) {
                const int r0 = m0 + g, r1 = r0 + 8;
                smf[OFF_SC / 4 + row * 208 + r0] =
                    ((mval >> (2 * slot)) & 1) ? (s_lo + b2v) : NEG_INF;
                if (r1 < T_DIM)
                    smf[OFF_SC / 4 + row * 208 + r1] =
                        ((mval >> (2 * slot + 1)) & 1) ? (s_hi + b2v) : NEG_INF;
            }
        }
    }
    __syncthreads();

    // ---- softmax: warps 0-3 -> row0, warps 4-7 -> row1; warp owns 50 scores ----
    const int srow = wid >> 2, w4 = wid & 3;
    const int t0 = w4 * 50;
    const int scb = OFF_SC / 4 + srow * 208;
    {
        float m = -1e38f;
        if (lane < 25) m = fmaxf(smf[scb + t0 + lane], smf[scb + t0 + 25 + lane]);
        #pragma unroll
        for (int o = 16; o; o >>= 1) m = fmaxf(m, __shfl_xor_sync(0xffffffffu, m, o));
        if (lane == 0) smf[OFF_RED / 4 + srow * 4 + w4] = m;
    }
    __syncthreads();
    float sinv;
    {
        float gm = fmaxf(fmaxf(smf[OFF_RED / 4 + srow * 4],     smf[OFF_RED / 4 + srow * 4 + 1]),
                         fmaxf(smf[OFF_RED / 4 + srow * 4 + 2], smf[OFF_RED / 4 + srow * 4 + 3]));
        float e0 = 0.0f, e1 = 0.0f;
        if (lane < 25) {
            e0 = __expf(smf[scb + t0 + lane] - gm);
            e1 = __expf(smf[scb + t0 + 25 + lane] - gm);
            smf[scb + t0 + lane] = e0;
            smf[scb + t0 + 25 + lane] = e1;
        }
        float s = e0 + e1;
        #pragma unroll
        for (int o = 16; o; o >>= 1) s += __shfl_xor_sync(0xffffffffu, s, o);
        if (lane == 0) smf[OFF_RED / 4 + 8 + srow * 4 + w4] = s;
        __syncthreads();
        float gs = (smf[OFF_RED / 4 + 8 + srow * 4]     + smf[OFF_RED / 4 + 8 + srow * 4 + 1]) +
                   (smf[OFF_RED / 4 + 8 + srow * 4 + 2] + smf[OFF_RED / 4 + 8 + srow * 4 + 3]);
        sinv = __fdividef(1.0f, gs);
    }

    // ---- weighted key sum: warp covers its row's keys [t0, t0+50) ----
    {
        float ax = 0.0f, ay = 0.0f;
        const uint32_t kbm = sbase + OFF_K + (uint32_t)(srow * 208 * KROW) + lane * 4;
        #pragma unroll 5
        for (int t = t0; t < t0 + 50; t++) {
            float p = smf[scb + t];
            uint32_t kv;
            asm("ld.shared.b32 %0,[%1];" : "=r"(kv) : "r"(kbm + t * KROW));
            float kx, ky;
            asm("{ .reg .b16 l, h; mov.b32 {l,h}, %2; cvt.f32.f16 %0, l; cvt.f32.f16 %1, h; }"
                : "=f"(kx), "=f"(ky) : "r"(kv));
            ax = fmaf(p, kx, ax);
            ay = fmaf(p, ky, ay);
        }
        float2 sc2 = make_float2(ax * sinv, ay * sinv);
        *(float2*)(sm + OFF_OP + srow * 1024 + w4 * 256 + lane * 8) = sc2;
    }
    __syncthreads();
    if (tid < 128) {
        const int orow = tid >> 6, d = tid & 63;
        float r = (smf[(OFF_OP + orow * 1024) / 4 + d] +
                   smf[(OFF_OP + orow * 1024 + 256) / 4 + d]) +
                  (smf[(OFF_OP + orow * 1024 + 512) / 4 + d] +
                   smf[(OFF_OP + orow * 1024 + 768) / 4 + d]);
        out[(size_t)(2 * b + orow) * 64 + d] = r;
    }
}

extern "C" void kernel_launch(void* const* d_in, const int* in_sizes, int n_in,
                              void* d_out, int out_size)
{
    const float*         query = (const float*)d_in[0];
    const float*         keys  = (const float*)d_in[1];
    const unsigned char* mask  = (const unsigned char*)d_in[2];
    const float*         W1    = (const float*)d_in[3];
    const float*         b1    = (const float*)d_in[4];
    const float*         W2    = (const float*)d_in[5];
    const float*         b2    = (const float*)d_in[6];
    float* out = (float*)d_out;

    setup_kernel<<<12, 256>>>(W1);
    cudaFuncSetAttribute(attn_pool_kernel,
                         cudaFuncAttributeMaxDynamicSharedMemorySize, SMEM_BYTES);
    attn_pool_kernel<<<B_DIM / 2, 256, SMEM_BYTES>>>(query, keys, mask, b1, W2, b2, out);
}

// round 13
// speedup vs baseline: 1.1442x; 1.1442x over previous
#include <cuda_runtime.h>
#include <cuda_fp16.h>
#include <cstdint>

#define B_DIM 4096
#define T_DIM 200
#define NEG_INF (-4294967295.0f)
#define KROW 144          // f16 key row stride bytes (36 words; 36 mod 32 = 4)

// smem byte offsets
#define OFF_K    0        // f16 keys, 208 rows x KROW (rows 200-207 zero)
#define OFF_QH   29952    // f32 qh[32]
#define OFF_W2   30080    // f32 w2[32]
#define OFF_SC   30208    // f32 scores[200] (pad 832)
#define OFF_RED  31040    // f32 red[16]
#define OFF_OP   31104    // float2 opart[8][32]
#define SMEM_BYTES 33152

__device__ float    g_wq[2048];    // W1a + W1c
__device__ uint32_t g_whi[1024];   // f16x2 fused weights, mma B-fragment order (R9 layout)
__device__ uint32_t g_wlo[1024];   // f16 residuals

__global__ __launch_bounds__(256)
void setup_kernel(const float* __restrict__ W1)
{
    const int tid = threadIdx.x, blk = blockIdx.x;
    if (blk < 8) {
        const int i = blk * 256 + tid;
        g_wq[i] = W1[i] + W1[4096 + i];
        return;
    }
    const int idx = (blk - 8) * 256 + tid;
    int d2 = idx >> 5, j = idx & 31, k = 2 * d2;
    float w0 = W1[2048 + k * 32 + j] - W1[4096 + k * 32 + j];
    float w1 = W1[2048 + (k + 1) * 32 + j] - W1[4096 + (k + 1) * 32 + j];
    uint32_t hi, lo;
    asm("cvt.rn.f16x2.f32 %0, %1, %2;" : "=r"(hi) : "f"(w1), "f"(w0));
    float h0f = __half2float(__ushort_as_half((unsigned short)(hi & 0xFFFFu)));
    float h1f = __half2float(__ushort_as_half((unsigned short)(hi >> 16)));
    asm("cvt.rn.f16x2.f32 %0, %1, %2;" : "=r"(lo) : "f"(w1 - h1f), "f"(w0 - h0f));
    int ks = d2 >> 3, k2 = d2 & 7, t4 = k2 & 3, sel = k2 >> 2;
    int word = ((ks * 4 + t4) * 32 + j) * 2 + sel;
    g_whi[word] = hi;
    g_wlo[word] = lo;
}

static __device__ __forceinline__ float sigmoidf_fast(float h) {
    return __fdividef(1.0f, 1.0f + __expf(-h));
}

__global__ __launch_bounds__(256, 4)
void attn_pool_kernel(const float* __restrict__ query,
                      const float* __restrict__ keys,
                      const unsigned char* __restrict__ mask_raw,
                      const float* __restrict__ b1,
                      const float* __restrict__ W2,
                      const float* __restrict__ b2,
                      float* __restrict__ out)
{
    extern __shared__ char sm[];
    float* smf = (float*)sm;
    const int b    = blockIdx.x;
    const int tid  = threadIdx.x;
    const int lane = tid & 31;
    const int wid  = tid >> 5;
    const int g    = lane >> 2;
    const int t4   = lane & 3;
    uint32_t sbase;
    asm("{ .reg .u64 t; cvta.to.shared.u64 t, %1; cvt.u32.u64 %0, t; }"
        : "=r"(sbase) : "l"(sm));
    const float4* kb = (const float4*)(keys + (size_t)b * (T_DIM * 64));

    // ---- per-warp self-staging: warp w stages ONLY its own tile rows ----
    #pragma unroll
    for (int mi = 0; mi < 2; mi++) {
        if (mi == 1 && wid >= 5) continue;
        const int m0 = (wid + 8 * mi) * 16;
        #pragma unroll
        for (int ii = 0; ii < 8; ii++) {
            int i = lane + ii * 32;
            int r = m0 + (i >> 4), c = i & 15;
            uint32_t p0 = 0u, p1 = 0u;
            if (r < T_DIM) {
                float4 v = __ldg(kb + r * 16 + c);
                asm("cvt.rn.f16x2.f32 %0,%1,%2;" : "=r"(p0) : "f"(v.y), "f"(v.x));
                asm("cvt.rn.f16x2.f32 %0,%1,%2;" : "=r"(p1) : "f"(v.w), "f"(v.z));
            }
            asm volatile("st.shared.v2.b32 [%0],{%1,%2};"
                         :: "r"(sbase + OFF_K + r * KROW + c * 8), "r"(p0), "r"(p1));
        }
    }

    // ---- warp 5: qh chain ; warp 6: w2 (balance the single-tile warps) ----
    if (wid == 5) {
        float q0 = query[b * 64 + lane];
        float q1 = query[b * 64 + 32 + lane];
        float s = b1[lane];
        #pragma unroll
        for (int d = 0; d < 32; d++)
            s = fmaf(__shfl_sync(0xffffffffu, q0, d), g_wq[d * 32 + lane], s);
        #pragma unroll
        for (int d = 0; d < 32; d++)
            s = fmaf(__shfl_sync(0xffffffffu, q1, d), g_wq[(32 + d) * 32 + lane], s);
        smf[OFF_QH / 4 + lane] = s;
    }
    if (wid == 6) smf[OFF_W2 / 4 + lane] = __ldg(W2 + lane);

    // ---- mask dtype detect + per-tile mask bits + b2 ----
    int my_nz = 0;
    #pragma unroll
    for (int w = lane; w < 256; w += 32)
        my_nz |= mask_raw[4 * w + 1] | mask_raw[4 * w + 2] | mask_raw[4 * w + 3];
    const bool mode_u8 = __any_sync(0xffffffffu, my_nz != 0);
    const int* mask_i32 = (const int*)mask_raw;
    const float b2v = __ldg(b2);

    int mval = 0;
    if (t4 == 0) {
        #pragma unroll
        for (int mi = 0; mi < 2; mi++) {
            if (mi == 1 && wid >= 5) continue;
            const int m0 = (wid + 8 * mi) * 16;
            const int r0 = m0 + g, r1 = r0 + 8;
            bool v0 = mode_u8 ? (mask_raw[b * T_DIM + r0] != 0)
                              : (mask_i32[b * T_DIM + r0] != 0);
            mval |= (int)v0 << (2 * mi);
            if (r1 < T_DIM) {
                bool v1 = mode_u8 ? (mask_raw[b * T_DIM + r1] != 0)
                                  : (mask_i32[b * T_DIM + r1] != 0);
                mval |= (int)v1 << (2 * mi + 1);
            }
        }
    }

    __syncwarp();   // warp's own STS visible to its own lanes' LDS (A fragments)

    // ====== score GEMM: m16n8k16 f16; A = own staged rows (smem), B = L2/L1 __ldg ======
    float acc[2][4][4];
    #pragma unroll
    for (int mi = 0; mi < 2; mi++)
        #pragma unroll
        for (int nt = 0; nt < 4; nt++)
            #pragma unroll
            for (int e = 0; e < 4; e++) acc[mi][nt][e] = 0.0f;

    const uint32_t wofs = (uint32_t)(t4 * 64 + g * 2);
    #pragma unroll
    for (int ks = 0; ks < 4; ks++) {
        uint2 bh[4], bl[4];
        #pragma unroll
        for (int nt = 0; nt < 4; nt++) {
            bh[nt] = __ldg((const uint2*)(g_whi + wofs + ks * 256 + nt * 16));
            bl[nt] = __ldg((const uint2*)(g_wlo + wofs + ks * 256 + nt * 16));
        }
        #pragma unroll
        for (int mi = 0; mi < 2; mi++) {
            if (mi == 1 && wid >= 5) continue;
            const int m0 = (wid + 8 * mi) * 16;
            const uint32_t abase = sbase + OFF_K +
                                   (uint32_t)((m0 + g) * KROW + ks * 32 + t4 * 4);
            uint32_t a0, a1, a2, a3;
            asm("ld.shared.b32 %0,[%1];" : "=r"(a0) : "r"(abase));
            asm("ld.shared.b32 %0,[%1];" : "=r"(a2) : "r"(abase + 16));
            asm("ld.shared.b32 %0,[%1];" : "=r"(a1) : "r"(abase + 8 * KROW));
            asm("ld.shared.b32 %0,[%1];" : "=r"(a3) : "r"(abase + 8 * KROW + 16));
            #pragma unroll
            for (int nt = 0; nt < 4; nt++) {
                asm volatile(
                    "mma.sync.aligned.m16n8k16.row.col.f32.f16.f16.f32 "
                    "{%0,%1,%2,%3}, {%4,%5,%6,%7}, {%8,%9}, {%0,%1,%2,%3};"
                    : "+f"(acc[mi][nt][0]), "+f"(acc[mi][nt][1]),
                      "+f"(acc[mi][nt][2]), "+f"(acc[mi][nt][3])
                    : "r"(a0), "r"(a1), "r"(a2), "r"(a3),
                      "r"(bh[nt].x), "r"(bh[nt].y));
                asm volatile(
                    "mma.sync.aligned.m16n8k16.row.col.f32.f16.f16.f32 "
                    "{%0,%1,%2,%3}, {%4,%5,%6,%7}, {%8,%9}, {%0,%1,%2,%3};"
                    : "+f"(acc[mi][nt][0]), "+f"(acc[mi][nt][1]),
                      "+f"(acc[mi][nt][2]), "+f"(acc[mi][nt][3])
                    : "r"(a0), "r"(a1), "r"(a2), "r"(a3),
                      "r"(bl[nt].x), "r"(bl[nt].y));
            }
        }
    }

    __syncthreads();   // qh/w2 visible; all warps' staged keys visible for weighted sum

    // ---- epilogue: h = C + qh ; sigmoid; dot W2; reduce over t4; mask ----
    #pragma unroll
    for (int mi = 0; mi < 2; mi++) {
        if (mi == 1 && wid >= 5) continue;
        const int m0 = (wid + 8 * mi) * 16;
        float s_lo = 0.0f, s_hi = 0.0f;
        #pragma unroll
        for (int nt = 0; nt < 4; nt++) {
            const int j0 = 8 * nt + 2 * t4;
            float2 qh2 = *(float2*)(sm + OFF_QH + j0 * 4);
            float2 w22 = *(float2*)(sm + OFF_W2 + j0 * 4);
            s_lo = fmaf(sigmoidf_fast(acc[mi][nt][0] + qh2.x), w22.x, s_lo);
            s_lo = fmaf(sigmoidf_fast(acc[mi][nt][1] + qh2.y), w22.y, s_lo);
            s_hi = fmaf(sigmoidf_fast(acc[mi][nt][2] + qh2.x), w22.x, s_hi);
            s_hi = fmaf(sigmoidf_fast(acc[mi][nt][3] + qh2.y), w22.y, s_hi);
        }
        s_lo += __shfl_xor_sync(0xffffffffu, s_lo, 1);
        s_lo += __shfl_xor_sync(0xffffffffu, s_lo, 2);
        s_hi += __shfl_xor_sync(0xffffffffu, s_hi, 1);
        s_hi += __shfl_xor_sync(0xffffffffu, s_hi, 2);
        if (t4 == 0) {
            const int r0 = m0 + g, r1 = r0 + 8;
            smf[OFF_SC / 4 + r0] = ((mval >> (2 * mi)) & 1) ? (s_lo + b2v) : NEG_INF;
            if (r1 < T_DIM)
                smf[OFF_SC / 4 + r1] = ((mval >> (2 * mi + 1)) & 1) ? (s_hi + b2v) : NEG_INF;
        }
    }
    __syncthreads();

    // ---- parallel softmax: warp w owns scores [25w, 25w+25) ----
    const int t0 = wid * 25;
    {
        float m = -1e38f;
        if (lane < 25) m = smf[OFF_SC / 4 + t0 + lane];
        #pragma unroll
        for (int o = 16; o; o >>= 1) m = fmaxf(m, __shfl_xor_sync(0xffffffffu, m, o));
        if (lane == 0) smf[OFF_RED / 4 + wid] = m;
    }
    __syncthreads();
    float sinv;
    {
        float gm = smf[OFF_RED / 4];
        #pragma unroll
        for (int p = 1; p < 8; p++) gm = fmaxf(gm, smf[OFF_RED / 4 + p]);
        float e = 0.0f;
        if (lane < 25) {
            e = __expf(smf[OFF_SC / 4 + t0 + lane] - gm);
            smf[OFF_SC / 4 + t0 + lane] = e;
        }
        float s = e;
        #pragma unroll
        for (int o = 16; o; o >>= 1) s += __shfl_xor_sync(0xffffffffu, s, o);
        if (lane == 0) smf[OFF_RED / 4 + 8 + wid] = s;
        __syncthreads();
        float gs = smf[OFF_RED / 4 + 8];
        #pragma unroll
        for (int p = 1; p < 8; p++) gs += smf[OFF_RED / 4 + 8 + p];
        sinv = __fdividef(1.0f, gs);
    }

    // ---- weighted key sum from f16 smem keys; lane owns d-pair (2lane, 2lane+1) ----
    {
        float ax = 0.0f, ay = 0.0f;
        #pragma unroll 5
        for (int t = t0; t < t0 + 25; t++) {
            float p = smf[OFF_SC / 4 + t];
            uint32_t kv;
            asm("ld.shared.b32 %0,[%1];" : "=r"(kv)
                : "r"(sbase + OFF_K + t * KROW + lane * 4));
            float kx, ky;
            asm("{ .reg .b16 l, h; mov.b32 {l,h}, %2; cvt.f32.f16 %0, l; cvt.f32.f16 %1, h; }"
                : "=f"(kx), "=f"(ky) : "r"(kv));
            ax = fmaf(p, kx, ax);
            ay = fmaf(p, ky, ay);
        }
        float2 sc2 = make_float2(ax * sinv, ay * sinv);
        *(float2*)(sm + OFF_OP + wid * 256 + lane * 8) = sc2;
    }
    __syncthreads();
    if (tid < 64) {
        float r = 0.0f;
        #pragma unroll
        for (int p = 0; p < 8; p++)
            r += smf[(OFF_OP + p * 256) / 4 + tid];
        out[b * 64 + tid] = r;
    }
}

extern "C" void kernel_launch(void* const* d_in, const int* in_sizes, int n_in,
                              void* d_out, int out_size)
{
    const float*         query = (const float*)d_in[0];
    const float*         keys  = (const float*)d_in[1];
    const unsigned char* mask  = (const unsigned char*)d_in[2];
    const float*         W1    = (const float*)d_in[3];
    const float*         b1    = (const float*)d_in[4];
    const float*         W2    = (const float*)d_in[5];
    const float*         b2    = (const float*)d_in[6];
    float* out = (float*)d_out;

    setup_kernel<<<12, 256>>>(W1);
    cudaFuncSetAttribute(attn_pool_kernel,
                         cudaFuncAttributeMaxDynamicSharedMemorySize, SMEM_BYTES);
    attn_pool_kernel<<<B_DIM, 256, SMEM_BYTES>>>(query, keys, mask, b1, W2, b2, out);
}